// round 13
// baseline (speedup 1.0000x reference)
#include <cuda_runtime.h>
#include <cstdint>
#include <cfloat>

#define NEG_SLOPE 0.01f

constexpr int Vv = 32, Fv = 16, Hv = 64;
constexpr int NG = 32 * 512;         // 16384 groups
constexpr int GPP = 4;               // groups per pass
constexpr int NPASS = NG / GPP;      // 4096
constexpr int THREADS = 256;
constexpr int STRIDE = 68;           // padded activation row stride (conflict-free LDS.128)
constexpr int GRID = 296;            // 2 blocks/SM * 148 SMs

// Shared float layout (107264 B -> 2 blocks/SM):
constexpr int OFF_W1  = 0;         // 1024
constexpr int OFF_W2  = 1024;      // 8192
constexpr int OFF_W3  = 9216;      // 8192
constexpr int OFF_B1  = 17408;
constexpr int OFF_B2  = 17472;
constexpr int OFF_B3  = 17536;
constexpr int OFF_PL1 = 17600;     // 256 [GPP][64]
constexpr int OFF_PL2 = 17856;     // 256
constexpr int OFF_BUF = 18112;     // 8704 [GPP][32][STRIDE] (in-place reuse)
constexpr int SMEM_FLOATS = 26816;
constexpr int SMEM_BYTES  = SMEM_FLOATS * 4;   // 107264

__device__ __forceinline__ float warp_max_f32(float v) {
    #pragma unroll
    for (int o = 16; o >= 1; o >>= 1)
        v = fmaxf(v, __shfl_xor_sync(0xffffffffu, v, o));
    return v;
}
__device__ __forceinline__ float warp_sum_f32(float v) {
    #pragma unroll
    for (int o = 16; o >= 1; o >>= 1)
        v += __shfl_xor_sync(0xffffffffu, v, o);
    return v;
}
__device__ __forceinline__ void ffma2(unsigned long long& d, unsigned long long a, unsigned long long b) {
    asm("fma.rn.f32x2 %0, %1, %2, %0;" : "+l"(d) : "l"(a), "l"(b));
}
__device__ __forceinline__ unsigned long long pack2(float lo, float hi) {
    unsigned long long r;
    asm("mov.b64 %0, {%1, %2};" : "=l"(r) : "f"(lo), "f"(hi));
    return r;
}
__device__ __forceinline__ float unpack_sum(unsigned long long v) {
    float lo, hi;
    asm("mov.b64 {%0, %1}, %2;" : "=f"(lo), "=f"(hi) : "l"(v));
    return lo + hi;
}

__global__ __launch_bounds__(THREADS, 2)
void fused_mlp_pool_kernel(const float* __restrict__ x,
                           const void*  __restrict__ maskp,
                           const float* __restrict__ W1,
                           const float* __restrict__ b1,
                           const float* __restrict__ W2,
                           const float* __restrict__ b2,
                           const float* __restrict__ W3,
                           const float* __restrict__ b3,
                           float* __restrict__ out)
{
    extern __shared__ float sm[];
    float* W1s = sm + OFF_W1;
    float* W2s = sm + OFF_W2;
    float* W3s = sm + OFF_W3;
    float* b1s = sm + OFF_B1;
    float* b2s = sm + OFF_B2;
    float* b3s = sm + OFF_B3;
    float* pl1 = sm + OFF_PL1;
    float* pl2 = sm + OFF_PL2;
    float* buf = sm + OFF_BUF;

    const int tid  = threadIdx.x;
    const int lane = tid & 31;      // = v
    const int warp = tid >> 5;      // 0..7
    const int hbase = warp * 8;

    // ---- stage weights into shared ----
    for (int i = tid; i < 1024; i += THREADS) W1s[i] = W1[i];
    for (int i = tid; i < 8192; i += THREADS) W2s[i] = W2[i];
    for (int i = tid; i < 8192; i += THREADS) W3s[i] = W3[i];
    if (tid < 64) { b1s[tid] = b1[tid]; b2s[tid] = b2[tid]; b3s[tid] = b3[tid]; }

    // ---- detect mask encoding (bool-u8 / int32 / float32) ----
    __shared__ int s_flags[4];
    if (tid < 4) s_flags[tid] = 0;
    __syncthreads();
    {
        int f0 = 0, f1 = 0, f23 = 0;
        const unsigned char* mb = (const unsigned char*)maskp;
        #pragma unroll
        for (int i = 0; i < 16; i++) {
            int idx = tid * 16 + i;
            unsigned char c = mb[idx];
            if (c) { int m = idx & 3; if (m == 0) f0 = 1; else if (m == 1) f1 = 1; else f23 = 1; }
        }
        if (f0)  atomicOr(&s_flags[0], 1);
        if (f1)  atomicOr(&s_flags[1], 1);
        if (f23) atomicOr(&s_flags[2], 1);
    }
    __syncthreads();
    const int fmt = s_flags[1] ? 1 : (s_flags[0] ? 0 : (s_flags[2] ? 2 : 0));

    for (int pass = blockIdx.x; pass < NPASS; pass += gridDim.x) {
        const int g0 = pass * GPP;

        bool valid[GPP], anyv[GPP];
        #pragma unroll
        for (int gi = 0; gi < GPP; gi++) {
            const int midx = (g0 + gi) * Vv + lane;
            bool v;
            if (fmt == 1)      v = ((const unsigned char*)maskp)[midx] != 0;
            else if (fmt == 0) v = ((const int*)maskp)[midx] != 0;
            else               v = ((const float*)maskp)[midx] != 0.0f;
            valid[gi] = v;
            anyv[gi]  = __ballot_sync(0xffffffffu, v) != 0;
        }

        // ---- x rows, viewed as packed f32x2 pairs (4 x ulonglong2 = 16 floats) ----
        ulonglong2 xr2[GPP][4];
        #pragma unroll
        for (int gi = 0; gi < GPP; gi++) {
            const ulonglong2* xp = (const ulonglong2*)(x + ((size_t)(g0 + gi) * Vv + lane) * Fv);
            xr2[gi][0] = xp[0]; xr2[gi][1] = xp[1]; xr2[gi][2] = xp[2]; xr2[gi][3] = xp[3];
        }

        float acc[GPP][8];

        // ================= Layer 1: 16 -> 64, packed along f =================
        #pragma unroll 2
        for (int hh = 0; hh < 8; hh++) {
            const ulonglong2* w = (const ulonglong2*)(W1s + (hbase + hh) * 16);
            ulonglong2 wA = w[0], wB = w[1], wC = w[2], wD = w[3];
            const float bb = b1s[hbase + hh];
            #pragma unroll
            for (int gi = 0; gi < GPP; gi++) {
                unsigned long long s2 = pack2(bb, 0.0f);
                ffma2(s2, xr2[gi][0].x, wA.x); ffma2(s2, xr2[gi][0].y, wA.y);
                ffma2(s2, xr2[gi][1].x, wB.x); ffma2(s2, xr2[gi][1].y, wB.y);
                ffma2(s2, xr2[gi][2].x, wC.x); ffma2(s2, xr2[gi][2].y, wC.y);
                ffma2(s2, xr2[gi][3].x, wD.x); ffma2(s2, xr2[gi][3].y, wD.y);
                acc[gi][hh] = unpack_sum(s2);
            }
        }
        // epilogue L1 -> buf, pl1
        #pragma unroll
        for (int gi = 0; gi < GPP; gi++) {
            float o[8], m[8];
            #pragma unroll
            for (int hh = 0; hh < 8; hh++) {
                float r = acc[gi][hh] > 0.0f ? acc[gi][hh] : NEG_SLOPE * acc[gi][hh];
                o[hh] = valid[gi] ? r : 0.0f;
                m[hh] = warp_max_f32(valid[gi] ? r : -FLT_MAX);
            }
            float* row = buf + gi * (Vv * STRIDE) + lane * STRIDE + hbase;
            *(float4*)(row)     = make_float4(o[0], o[1], o[2], o[3]);
            *(float4*)(row + 4) = make_float4(o[4], o[5], o[6], o[7]);
            if (lane == 0) {
                float* pp = pl1 + gi * 64 + hbase;
                *(float4*)(pp)     = make_float4(anyv[gi] ? m[0] : 0.0f, anyv[gi] ? m[1] : 0.0f,
                                                 anyv[gi] ? m[2] : 0.0f, anyv[gi] ? m[3] : 0.0f);
                *(float4*)(pp + 4) = make_float4(anyv[gi] ? m[4] : 0.0f, anyv[gi] ? m[5] : 0.0f,
                                                 anyv[gi] ? m[6] : 0.0f, anyv[gi] ? m[7] : 0.0f);
            }
        }
        __syncthreads();   // sync1: L1 writes -> L2 reads

        // ================= Layer 2: 128 -> 64, packed along j =================
        {   // pool-side constant
            float2 wp[8];
            #pragma unroll
            for (int hh = 0; hh < 8; hh++)
                wp[hh] = *(const float2*)(W2s + (hbase + hh) * 128 + 64 + 2 * lane);
            #pragma unroll
            for (int gi = 0; gi < GPP; gi++) {
                float2 pp = *(const float2*)(pl1 + gi * 64 + 2 * lane);
                #pragma unroll
                for (int hh = 0; hh < 8; hh++)
                    acc[gi][hh] = warp_sum_f32(pp.x * wp[hh].x + pp.y * wp[hh].y) + b2s[hbase + hh];
            }
        }
        {
            unsigned long long acc2[GPP][8];
            #pragma unroll
            for (int gi = 0; gi < GPP; gi++)
                #pragma unroll
                for (int hh = 0; hh < 8; hh++)
                    acc2[gi][hh] = pack2(acc[gi][hh], 0.0f);
            #pragma unroll 2
            for (int j = 0; j < 64; j += 4) {
                ulonglong2 a2[GPP];
                #pragma unroll
                for (int gi = 0; gi < GPP; gi++)
                    a2[gi] = *(const ulonglong2*)(buf + gi * (Vv * STRIDE) + lane * STRIDE + j);
                #pragma unroll
                for (int hh = 0; hh < 8; hh++) {
                    ulonglong2 wv = *(const ulonglong2*)(W2s + (hbase + hh) * 128 + j);
                    #pragma unroll
                    for (int gi = 0; gi < GPP; gi++) {
                        ffma2(acc2[gi][hh], a2[gi].x, wv.x);
                        ffma2(acc2[gi][hh], a2[gi].y, wv.y);
                    }
                }
            }
            #pragma unroll
            for (int gi = 0; gi < GPP; gi++)
                #pragma unroll
                for (int hh = 0; hh < 8; hh++)
                    acc[gi][hh] = unpack_sum(acc2[gi][hh]);
        }
        __syncthreads();   // sync2: L2 reads of buf complete before in-place writes

        // epilogue L2 -> buf (in place), pl2
        #pragma unroll
        for (int gi = 0; gi < GPP; gi++) {
            float o[8], m[8];
            #pragma unroll
            for (int hh = 0; hh < 8; hh++) {
                float r = acc[gi][hh] > 0.0f ? acc[gi][hh] : NEG_SLOPE * acc[gi][hh];
                o[hh] = valid[gi] ? r : 0.0f;
                m[hh] = warp_max_f32(valid[gi] ? r : -FLT_MAX);
            }
            float* row = buf + gi * (Vv * STRIDE) + lane * STRIDE + hbase;
            *(float4*)(row)     = make_float4(o[0], o[1], o[2], o[3]);
            *(float4*)(row + 4) = make_float4(o[4], o[5], o[6], o[7]);
            if (lane == 0) {
                float* pp = pl2 + gi * 64 + hbase;
                *(float4*)(pp)     = make_float4(anyv[gi] ? m[0] : 0.0f, anyv[gi] ? m[1] : 0.0f,
                                                 anyv[gi] ? m[2] : 0.0f, anyv[gi] ? m[3] : 0.0f);
                *(float4*)(pp + 4) = make_float4(anyv[gi] ? m[4] : 0.0f, anyv[gi] ? m[5] : 0.0f,
                                                 anyv[gi] ? m[6] : 0.0f, anyv[gi] ? m[7] : 0.0f);
            }
        }
        __syncthreads();   // sync3: L2 writes -> L3 reads

        // ================= Layer 3: 128 -> 64 (pool only), packed along j =================
        {
            float2 wp[8];
            #pragma unroll
            for (int hh = 0; hh < 8; hh++)
                wp[hh] = *(const float2*)(W3s + (hbase + hh) * 128 + 64 + 2 * lane);
            #pragma unroll
            for (int gi = 0; gi < GPP; gi++) {
                float2 pp = *(const float2*)(pl2 + gi * 64 + 2 * lane);
                #pragma unroll
                for (int hh = 0; hh < 8; hh++)
                    acc[gi][hh] = warp_sum_f32(pp.x * wp[hh].x + pp.y * wp[hh].y) + b3s[hbase + hh];
            }
        }
        {
            unsigned long long acc2[GPP][8];
            #pragma unroll
            for (int gi = 0; gi < GPP; gi++)
                #pragma unroll
                for (int hh = 0; hh < 8; hh++)
                    acc2[gi][hh] = pack2(acc[gi][hh], 0.0f);
            #pragma unroll 2
            for (int j = 0; j < 64; j += 4) {
                ulonglong2 a2[GPP];
                #pragma unroll
                for (int gi = 0; gi < GPP; gi++)
                    a2[gi] = *(const ulonglong2*)(buf + gi * (Vv * STRIDE) + lane * STRIDE + j);
                #pragma unroll
                for (int hh = 0; hh < 8; hh++) {
                    ulonglong2 wv = *(const ulonglong2*)(W3s + (hbase + hh) * 128 + j);
                    #pragma unroll
                    for (int gi = 0; gi < GPP; gi++) {
                        ffma2(acc2[gi][hh], a2[gi].x, wv.x);
                        ffma2(acc2[gi][hh], a2[gi].y, wv.y);
                    }
                }
            }
            #pragma unroll
            for (int gi = 0; gi < GPP; gi++)
                #pragma unroll
                for (int hh = 0; hh < 8; hh++)
                    acc[gi][hh] = unpack_sum(acc2[gi][hh]);
        }
        // final epilogue: pool3 -> out
        #pragma unroll
        for (int gi = 0; gi < GPP; gi++) {
            float m[8];
            #pragma unroll
            for (int hh = 0; hh < 8; hh++) {
                float r = acc[gi][hh] > 0.0f ? acc[gi][hh] : NEG_SLOPE * acc[gi][hh];
                m[hh] = warp_max_f32(valid[gi] ? r : -FLT_MAX);
            }
            if (lane == 0) {
                float* op = out + (size_t)(g0 + gi) * Hv + hbase;
                *(float4*)(op)     = make_float4(anyv[gi] ? m[0] : 0.0f, anyv[gi] ? m[1] : 0.0f,
                                                 anyv[gi] ? m[2] : 0.0f, anyv[gi] ? m[3] : 0.0f);
                *(float4*)(op + 4) = make_float4(anyv[gi] ? m[4] : 0.0f, anyv[gi] ? m[5] : 0.0f,
                                                 anyv[gi] ? m[6] : 0.0f, anyv[gi] ? m[7] : 0.0f);
            }
        }
        __syncthreads();   // sync4: L3 reads of buf complete before next pass's L1 writes
    }
}

extern "C" void kernel_launch(void* const* d_in, const int* in_sizes, int n_in,
                              void* d_out, int out_size)
{
    const float* x  = (const float*)d_in[0];
    const void*  mk = d_in[1];
    const float* W1 = (const float*)d_in[2];
    const float* b1 = (const float*)d_in[3];
    const float* W2 = (const float*)d_in[4];
    const float* b2 = (const float*)d_in[5];
    const float* W3 = (const float*)d_in[6];
    const float* b3 = (const float*)d_in[7];
    float* out = (float*)d_out;

    cudaFuncSetAttribute(fused_mlp_pool_kernel,
                         cudaFuncAttributeMaxDynamicSharedMemorySize, SMEM_BYTES);
    fused_mlp_pool_kernel<<<GRID, THREADS, SMEM_BYTES>>>(x, mk, W1, b1, W2, b2, W3, b3, out);
}

// round 15
// speedup vs baseline: 1.7069x; 1.7069x over previous
#include <cuda_runtime.h>
#include <cstdint>
#include <cfloat>

#define NEG_SLOPE 0.01f

constexpr int Vv = 32, Fv = 16, Hv = 64;
constexpr int NG = 16384;            // (b,p) groups
constexpr int GPP = 4;               // groups per pass
constexpr int NPASS = NG / GPP;      // 4096
constexpr int THREADS = 256;
constexpr int STRIDE = 68;           // padded activation row stride (proven conflict-free)
constexpr int GRID = 444;            // 3 blocks/SM * 148 SMs

// Shared float layout (74496 B -> 3 blocks/SM):
//  W1s [1024] | W2o [4096] (out-half [h][64]) | W3o [4096] | b1,b2,b3 [192]
//  pl1 [256] | pl2 [256] | buf [4*32*68 = 8704]
constexpr int OFF_W1  = 0;
constexpr int OFF_W2O = 1024;
constexpr int OFF_W3O = 5120;
constexpr int OFF_B1  = 9216;
constexpr int OFF_B2  = 9280;
constexpr int OFF_B3  = 9344;
constexpr int OFF_PL1 = 9408;
constexpr int OFF_PL2 = 9664;
constexpr int OFF_BUF = 9920;
constexpr int SMEM_FLOATS = 18624;
constexpr int SMEM_BYTES  = SMEM_FLOATS * 4;   // 74496

__device__ __forceinline__ float warp_max_f32(float v) {
    #pragma unroll
    for (int o = 16; o >= 1; o >>= 1)
        v = fmaxf(v, __shfl_xor_sync(0xffffffffu, v, o));
    return v;
}
__device__ __forceinline__ float warp_sum_f32(float v) {
    #pragma unroll
    for (int o = 16; o >= 1; o >>= 1)
        v += __shfl_xor_sync(0xffffffffu, v, o);
    return v;
}

__global__ __launch_bounds__(THREADS, 3)
void fused_mlp_pool_kernel(const float* __restrict__ x,
                           const void*  __restrict__ maskp,
                           const float* __restrict__ W1,
                           const float* __restrict__ b1,
                           const float* __restrict__ W2,
                           const float* __restrict__ b2,
                           const float* __restrict__ W3,
                           const float* __restrict__ b3,
                           float* __restrict__ out)
{
    extern __shared__ float sm[];
    float* W1s = sm + OFF_W1;
    float* W2o = sm + OFF_W2O;
    float* W3o = sm + OFF_W3O;
    float* b1s = sm + OFF_B1;
    float* b2s = sm + OFF_B2;
    float* b3s = sm + OFF_B3;
    float* pl1 = sm + OFF_PL1;
    float* pl2 = sm + OFF_PL2;
    float* buf = sm + OFF_BUF;

    const int tid  = threadIdx.x;
    const int lane = tid & 31;      // = v
    const int warp = tid >> 5;      // 0..7
    const int hbase = warp * 8;

    // ---- stage W1 + OUT-halves of W2/W3 + biases into shared ----
    for (int i = tid; i < 1024; i += THREADS) W1s[i] = W1[i];
    for (int i = tid; i < 4096; i += THREADS) {
        int h = i >> 6, j = i & 63;
        W2o[i] = W2[h * 128 + j];
        W3o[i] = W3[h * 128 + j];
    }
    if (tid < 64) { b1s[tid] = b1[tid]; b2s[tid] = b2[tid]; b3s[tid] = b3[tid]; }

    // ---- detect mask encoding (bool-u8 / int32 / float32) ----
    __shared__ int s_flags[4];
    if (tid < 4) s_flags[tid] = 0;
    __syncthreads();
    {
        int f0 = 0, f1 = 0, f23 = 0;
        const unsigned char* mb = (const unsigned char*)maskp;
        #pragma unroll
        for (int i = 0; i < 16; i++) {
            int idx = tid * 16 + i;
            unsigned char c = mb[idx];
            if (c) { int m = idx & 3; if (m == 0) f0 = 1; else if (m == 1) f1 = 1; else f23 = 1; }
        }
        if (f0)  atomicOr(&s_flags[0], 1);
        if (f1)  atomicOr(&s_flags[1], 1);
        if (f23) atomicOr(&s_flags[2], 1);
    }
    __syncthreads();
    const int fmt = s_flags[1] ? 1 : (s_flags[0] ? 0 : (s_flags[2] ? 2 : 0));

    // Per-warp global pointers for the pool-half columns (L1-resident after pass 1).
    const float* W2p_g = W2 + 64 + 2 * lane;   // + h*128
    const float* W3p_g = W3 + 64 + 2 * lane;

    for (int pass = blockIdx.x; pass < NPASS; pass += gridDim.x) {
        const int g0 = pass * GPP;

        bool valid[GPP], anyv[GPP];
        #pragma unroll
        for (int gi = 0; gi < GPP; gi++) {
            const int midx = (g0 + gi) * Vv + lane;
            bool v;
            if (fmt == 1)      v = ((const unsigned char*)maskp)[midx] != 0;
            else if (fmt == 0) v = ((const int*)maskp)[midx] != 0;
            else               v = ((const float*)maskp)[midx] != 0.0f;
            valid[gi] = v;
            anyv[gi]  = __ballot_sync(0xffffffffu, v) != 0;
        }

        // ================= Layer 1: 16 -> 64, processed per group (low reg peak) =================
        #pragma unroll 1
        for (int gi = 0; gi < GPP; gi++) {
            const float4* xp = (const float4*)(x + ((size_t)(g0 + gi) * Vv + lane) * Fv);
            float4 x0 = xp[0], x1 = xp[1], x2 = xp[2], x3 = xp[3];
            float o[8], m[8];
            #pragma unroll
            for (int hh = 0; hh < 8; hh++) {
                const float4* w = (const float4*)(W1s + (hbase + hh) * 16);
                float4 w0 = w[0], w1 = w[1], w2 = w[2], w3 = w[3];
                float s = b1s[hbase + hh];
                s = fmaf(x0.x, w0.x, s); s = fmaf(x0.y, w0.y, s); s = fmaf(x0.z, w0.z, s); s = fmaf(x0.w, w0.w, s);
                s = fmaf(x1.x, w1.x, s); s = fmaf(x1.y, w1.y, s); s = fmaf(x1.z, w1.z, s); s = fmaf(x1.w, w1.w, s);
                s = fmaf(x2.x, w2.x, s); s = fmaf(x2.y, w2.y, s); s = fmaf(x2.z, w2.z, s); s = fmaf(x2.w, w2.w, s);
                s = fmaf(x3.x, w3.x, s); s = fmaf(x3.y, w3.y, s); s = fmaf(x3.z, w3.z, s); s = fmaf(x3.w, w3.w, s);
                float r = s > 0.0f ? s : NEG_SLOPE * s;
                o[hh] = valid[gi] ? r : 0.0f;
                m[hh] = warp_max_f32(valid[gi] ? r : -FLT_MAX);
            }
            float* row = buf + gi * (Vv * STRIDE) + lane * STRIDE + hbase;
            *(float4*)(row)     = make_float4(o[0], o[1], o[2], o[3]);
            *(float4*)(row + 4) = make_float4(o[4], o[5], o[6], o[7]);
            if (lane == 0) {
                float* pp = pl1 + gi * 64 + hbase;
                *(float4*)(pp)     = make_float4(anyv[gi] ? m[0] : 0.0f, anyv[gi] ? m[1] : 0.0f,
                                                 anyv[gi] ? m[2] : 0.0f, anyv[gi] ? m[3] : 0.0f);
                *(float4*)(pp + 4) = make_float4(anyv[gi] ? m[4] : 0.0f, anyv[gi] ? m[5] : 0.0f,
                                                 anyv[gi] ? m[6] : 0.0f, anyv[gi] ? m[7] : 0.0f);
            }
        }
        __syncthreads();   // sync1: L1 writes -> L2 reads

        float acc[GPP][8];

        // ================= Layer 2: 128 -> 64 =================
        {   // pool-side constant from GLOBAL pool-half weights (L1-cached)
            #pragma unroll
            for (int hh = 0; hh < 8; hh++) {
                float2 wp = __ldg((const float2*)(W2p_g + (hbase + hh) * 128));
                #pragma unroll
                for (int gi = 0; gi < GPP; gi++) {
                    float2 pp = *(const float2*)(pl1 + gi * 64 + 2 * lane);
                    acc[gi][hh] = warp_sum_f32(pp.x * wp.x + pp.y * wp.y) + b2s[hbase + hh];
                }
            }
        }
        #pragma unroll 2
        for (int j = 0; j < 64; j += 4) {
            float4 a[GPP];
            #pragma unroll
            for (int gi = 0; gi < GPP; gi++)
                a[gi] = *(const float4*)(buf + gi * (Vv * STRIDE) + lane * STRIDE + j);
            #pragma unroll
            for (int hc = 0; hc < 2; hc++) {            // 4-h weight chunks: lower reg peak
                float4 w[4];
                #pragma unroll
                for (int hh = 0; hh < 4; hh++)
                    w[hh] = *(const float4*)(W2o + (hbase + hc * 4 + hh) * 64 + j);
                #pragma unroll
                for (int gi = 0; gi < GPP; gi++)
                    #pragma unroll
                    for (int hh = 0; hh < 4; hh++)
                        acc[gi][hc * 4 + hh] = fmaf(a[gi].x, w[hh].x, fmaf(a[gi].y, w[hh].y,
                                               fmaf(a[gi].z, w[hh].z, fmaf(a[gi].w, w[hh].w,
                                                    acc[gi][hc * 4 + hh]))));
            }
        }
        __syncthreads();   // sync2: L2 reads done before in-place writes

        // epilogue L2 -> buf (in place), pl2
        #pragma unroll
        for (int gi = 0; gi < GPP; gi++) {
            float o[8], m[8];
            #pragma unroll
            for (int hh = 0; hh < 8; hh++) {
                float r = acc[gi][hh] > 0.0f ? acc[gi][hh] : NEG_SLOPE * acc[gi][hh];
                o[hh] = valid[gi] ? r : 0.0f;
                m[hh] = warp_max_f32(valid[gi] ? r : -FLT_MAX);
            }
            float* row = buf + gi * (Vv * STRIDE) + lane * STRIDE + hbase;
            *(float4*)(row)     = make_float4(o[0], o[1], o[2], o[3]);
            *(float4*)(row + 4) = make_float4(o[4], o[5], o[6], o[7]);
            if (lane == 0) {
                float* pp = pl2 + gi * 64 + hbase;
                *(float4*)(pp)     = make_float4(anyv[gi] ? m[0] : 0.0f, anyv[gi] ? m[1] : 0.0f,
                                                 anyv[gi] ? m[2] : 0.0f, anyv[gi] ? m[3] : 0.0f);
                *(float4*)(pp + 4) = make_float4(anyv[gi] ? m[4] : 0.0f, anyv[gi] ? m[5] : 0.0f,
                                                 anyv[gi] ? m[6] : 0.0f, anyv[gi] ? m[7] : 0.0f);
            }
        }
        __syncthreads();   // sync3: L2 writes -> L3 reads

        // ================= Layer 3: 128 -> 64 (pool only) =================
        {
            #pragma unroll
            for (int hh = 0; hh < 8; hh++) {
                float2 wp = __ldg((const float2*)(W3p_g + (hbase + hh) * 128));
                #pragma unroll
                for (int gi = 0; gi < GPP; gi++) {
                    float2 pp = *(const float2*)(pl2 + gi * 64 + 2 * lane);
                    acc[gi][hh] = warp_sum_f32(pp.x * wp.x + pp.y * wp.y) + b3s[hbase + hh];
                }
            }
        }
        #pragma unroll 2
        for (int j = 0; j < 64; j += 4) {
            float4 a[GPP];
            #pragma unroll
            for (int gi = 0; gi < GPP; gi++)
                a[gi] = *(const float4*)(buf + gi * (Vv * STRIDE) + lane * STRIDE + j);
            #pragma unroll
            for (int hc = 0; hc < 2; hc++) {
                float4 w[4];
                #pragma unroll
                for (int hh = 0; hh < 4; hh++)
                    w[hh] = *(const float4*)(W3o + (hbase + hc * 4 + hh) * 64 + j);
                #pragma unroll
                for (int gi = 0; gi < GPP; gi++)
                    #pragma unroll
                    for (int hh = 0; hh < 4; hh++)
                        acc[gi][hc * 4 + hh] = fmaf(a[gi].x, w[hh].x, fmaf(a[gi].y, w[hh].y,
                                               fmaf(a[gi].z, w[hh].z, fmaf(a[gi].w, w[hh].w,
                                                    acc[gi][hc * 4 + hh]))));
            }
        }
        // final epilogue: pool3 -> out
        #pragma unroll
        for (int gi = 0; gi < GPP; gi++) {
            float m[8];
            #pragma unroll
            for (int hh = 0; hh < 8; hh++) {
                float r = acc[gi][hh] > 0.0f ? acc[gi][hh] : NEG_SLOPE * acc[gi][hh];
                m[hh] = warp_max_f32(valid[gi] ? r : -FLT_MAX);
            }
            if (lane == 0) {
                float* op = out + (size_t)(g0 + gi) * Hv + hbase;
                *(float4*)(op)     = make_float4(anyv[gi] ? m[0] : 0.0f, anyv[gi] ? m[1] : 0.0f,
                                                 anyv[gi] ? m[2] : 0.0f, anyv[gi] ? m[3] : 0.0f);
                *(float4*)(op + 4) = make_float4(anyv[gi] ? m[4] : 0.0f, anyv[gi] ? m[5] : 0.0f,
                                                 anyv[gi] ? m[6] : 0.0f, anyv[gi] ? m[7] : 0.0f);
            }
        }
        __syncthreads();   // sync4: L3 reads done before next pass's L1 writes
    }
}

extern "C" void kernel_launch(void* const* d_in, const int* in_sizes, int n_in,
                              void* d_out, int out_size)
{
    const float* x  = (const float*)d_in[0];
    const void*  mk = d_in[1];
    const float* W1 = (const float*)d_in[2];
    const float* b1 = (const float*)d_in[3];
    const float* W2 = (const float*)d_in[4];
    const float* b2 = (const float*)d_in[5];
    const float* W3 = (const float*)d_in[6];
    const float* b3 = (const float*)d_in[7];
    float* out = (float*)d_out;

    cudaFuncSetAttribute(fused_mlp_pool_kernel,
                         cudaFuncAttributeMaxDynamicSharedMemorySize, SMEM_BYTES);
    fused_mlp_pool_kernel<<<GRID, THREADS, SMEM_BYTES>>>(x, mk, W1, b1, W2, b2, W3, b3, out);
}